// round 7
// baseline (speedup 1.0000x reference)
#include <cuda_runtime.h>

// Problem dims
#define S_LEN  512
#define BATCH  256
#define IN_DIM 256
#define BR_DIM 128
#define HID    512
#define G4     2048   // 4*HID

// Tiling
#define NBLK      128        // 8 batch-tiles x 16 h-tiles, <=148 SMs -> all resident
#define NTHR      256
#define AS_STRIDE 36         // 32 + pad
#define WS_STRIDE 132        // 128 + pad

// Scratch (static device allocations only — no cudaMalloc anywhere)
__device__ float g_hs0[(size_t)S_LEN * BATCH * HID];  // layer-0 hidden sequence (256 MB)
__device__ float g_hbuf[2 * BATCH * HID];             // double-buffered h state
__device__ float g_c[BATCH * HID];                    // c state (thread-private access pattern)
__device__ unsigned g_cnt = 0;
__device__ unsigned g_gen = 0;

// ---------- packed f32x2 helpers ----------
__device__ __forceinline__ unsigned long long pk2(float lo, float hi) {
    unsigned long long r;
    asm("mov.b64 %0, {%1, %2};" : "=l"(r) : "f"(lo), "f"(hi));
    return r;
}
__device__ __forceinline__ void upk2(unsigned long long v, float& lo, float& hi) {
    asm("mov.b64 {%0, %1}, %2;" : "=f"(lo), "=f"(hi) : "l"(v));
}
__device__ __forceinline__ void fma2(unsigned long long& d, unsigned long long a, unsigned long long b) {
    asm("fma.rn.f32x2 %0, %1, %2, %0;" : "+l"(d) : "l"(a), "l"(b));
}

__device__ __forceinline__ float sigf(float x) { return 1.0f / (1.0f + expf(-x)); }

// ---------- fenced grid barrier (all NBLK blocks resident by construction) ----------
__device__ __forceinline__ void grid_sync() {
    __syncthreads();
    if (threadIdx.x == 0) {
        unsigned gen = atomicAdd(&g_gen, 0u);
        __threadfence();
        if (atomicAdd(&g_cnt, 1u) == NBLK - 1u) {
            atomicExch(&g_cnt, 0u);
            __threadfence();
            atomicAdd(&g_gen, 1u);
        } else {
            while (atomicAdd(&g_gen, 0u) == gen) { __nanosleep(64); }
        }
    }
    __syncthreads();
}

// ---------- 32x32 k-chunk rank-update: tile [32 b] x [128 gate-cols], f32x2 packed ----------
__device__ __forceinline__ void mma_chunk(const float* As, const float* Ws,
                                          int tx, int ty, unsigned long long acc[8]) {
#pragma unroll
    for (int kk = 0; kk < 32; ++kk) {
        const float4 a4 = *(const float4*)(As + kk * AS_STRIDE + ty * 4);
        const float4 w4 = *(const float4*)(Ws + kk * WS_STRIDE + tx * 4);
        unsigned long long w0 = pk2(w4.x, w4.y);
        unsigned long long w1 = pk2(w4.z, w4.w);
        unsigned long long a;
        a = pk2(a4.x, a4.x); fma2(acc[0], a, w0); fma2(acc[1], a, w1);
        a = pk2(a4.y, a4.y); fma2(acc[2], a, w0); fma2(acc[3], a, w1);
        a = pk2(a4.z, a4.z); fma2(acc[4], a, w0); fma2(acc[5], a, w1);
        a = pk2(a4.w, a4.w); fma2(acc[6], a, w0); fma2(acc[7], a, w1);
    }
}

// ---------- one K-segment of the fused per-step GEMM, double-buffered ----------
// A: [32 rows of this block's batch tile] x [Kseg], row stride lda (pre-offset by b0*lda)
// W: [Ktotal_seg rows] x [2048]; this block uses cols {g*512 + h0 + 0..31, g=0..3}
__device__ __forceinline__ void gemm_segment(
    const float* __restrict__ A, int lda,
    const float* __restrict__ W, int nchunk, int h0,
    unsigned long long acc[8],
    float* As0, float* As1, float* Ws0, float* Ws1)
{
    const int tid = threadIdx.x;
    const int tx = tid & 31, ty = tid >> 5;
    const int r = tid >> 3, q = tid & 7;          // A-load: row r, float4 q
    const int np = tid & 127;                     // W-load: gate-col index 0..127
    const int kk0 = tid >> 7;                     // 0/1 (two k rows per pass)
    const int woff = ((np >> 5) << 9) + (np & 31) + h0;  // actual column in [0,2048)

    const float* Arow = A + (size_t)r * lda + q * 4;

    float4 av;
    float wv[16];

    // prologue: chunk 0 -> buf0
    av = __ldcg((const float4*)Arow);
    {
        const float* Wb = W + woff + (size_t)kk0 * G4;
#pragma unroll
        for (int it = 0; it < 16; ++it) wv[it] = __ldg(Wb + (size_t)(2 * it) * G4);
    }
    {
        float* d = As0 + q * 4 * AS_STRIDE + r;
        d[0] = av.x; d[AS_STRIDE] = av.y; d[2 * AS_STRIDE] = av.z; d[3 * AS_STRIDE] = av.w;
        float* wd = Ws0 + kk0 * WS_STRIDE + np;
#pragma unroll
        for (int it = 0; it < 16; ++it) wd[2 * it * WS_STRIDE] = wv[it];
    }

    for (int c = 0; c < nchunk; ++c) {
        __syncthreads();
        const float* Ac = (c & 1) ? As1 : As0;
        const float* Wc = (c & 1) ? Ws1 : Ws0;
        if (c + 1 < nchunk) {
            av = __ldcg((const float4*)(Arow + (c + 1) * 32));
            const float* Wb = W + woff + ((size_t)(c + 1) * 32 + kk0) * G4;
#pragma unroll
            for (int it = 0; it < 16; ++it) wv[it] = __ldg(Wb + (size_t)(2 * it) * G4);
        }
        mma_chunk(Ac, Wc, tx, ty, acc);
        if (c + 1 < nchunk) {
            float* An = (c & 1) ? As0 : As1;
            float* Wn = (c & 1) ? Ws0 : Ws1;
            float* d = An + q * 4 * AS_STRIDE + r;
            d[0] = av.x; d[AS_STRIDE] = av.y; d[2 * AS_STRIDE] = av.z; d[3 * AS_STRIDE] = av.w;
            float* wd = Wn + kk0 * WS_STRIDE + np;
#pragma unroll
            for (int it = 0; it < 16; ++it) wd[2 * it * WS_STRIDE] = wv[it];
        }
    }
}

// ---------- gate nonlinearity + state update (all 4 gates owned by this block) ----------
__device__ __forceinline__ void step_tail(
    unsigned long long acc[8], float* Gs,
    const float* __restrict__ bias, int b0, int h0,
    float* __restrict__ hwrite, float* __restrict__ seq_out_t,
    float* __restrict__ hn_out, float* __restrict__ cn_out, bool last)
{
    const int tid = threadIdx.x;
    const int tx = tid & 31, ty = tid >> 5;

    // stage gate tile [32 m][128 n'] into shared (buf0 — disjoint from last compute buf1)
#pragma unroll
    for (int i = 0; i < 4; ++i) {
        float lo0, hi0, lo1, hi1;
        upk2(acc[2 * i],     lo0, hi0);
        upk2(acc[2 * i + 1], lo1, hi1);
        *(float4*)(Gs + (ty * 4 + i) * WS_STRIDE + tx * 4) = make_float4(lo0, hi0, lo1, hi1);
    }
    __syncthreads();

#pragma unroll
    for (int u = 0; u < 4; ++u) {
        const int idx = tid + NTHR * u;   // 0..1023 -> (m, hh)
        const int m = idx >> 5, hh = idx & 31;
        const int col = h0 + hh;
        const float* row = Gs + m * WS_STRIDE;
        float ii = row[hh]          + __ldg(bias + col);
        float ff = row[32 + hh]     + __ldg(bias + 512 + col);
        float gg = row[64 + hh]     + __ldg(bias + 1024 + col);
        float oo = row[96 + hh]     + __ldg(bias + 1536 + col);
        const size_t sidx = (size_t)(b0 + m) * HID + col;
        float c_old = g_c[sidx];
        float cn = sigf(ff) * c_old + sigf(ii) * tanhf(gg);
        float hn = sigf(oo) * tanhf(cn);
        g_c[sidx] = cn;
        hwrite[sidx] = hn;
        seq_out_t[sidx] = hn;
        if (last) { hn_out[sidx] = hn; cn_out[sidx] = cn; }
    }
    // no trailing __syncthreads needed: grid_sync() follows and begins with one
}

__device__ __forceinline__ void zero_state(int b0, int h0) {
    const int tid = threadIdx.x;
#pragma unroll
    for (int u = 0; u < 4; ++u) {
        const int idx = tid + NTHR * u;
        const int m = idx >> 5, hh = idx & 31;
        const size_t sidx = (size_t)(b0 + m) * HID + h0 + hh;
        g_c[sidx] = 0.0f;
        g_hbuf[sidx] = 0.0f;     // buffer 0 (read at t=0)
    }
}

__global__ __launch_bounds__(NTHR, 1)
void lstm_persistent(
    const float* __restrict__ x,     const float* __restrict__ br,
    const float* __restrict__ Wih0,  const float* __restrict__ Wbh0,
    const float* __restrict__ Whh0,  const float* __restrict__ bias0,
    const float* __restrict__ Wih1,  const float* __restrict__ Whh1,
    const float* __restrict__ bias1, float* __restrict__ out)
{
    __shared__ float sAs[2][32 * AS_STRIDE];
    __shared__ float sWs[2][32 * WS_STRIDE];   // sWs[0] doubles as the gate-staging tile

    const int bid = blockIdx.x;
    const int b0 = (bid >> 4) * 32;   // 8 batch tiles
    const int h0 = (bid & 15) * 32;   // 16 hidden tiles
    const size_t BH = (size_t)BATCH * HID;
    const size_t OFF_HN = (size_t)S_LEN * BH;
    const size_t OFF_CN = OFF_HN + 2 * BH;

    // ---------------- layer 0 (bridge cell): K = 256(x) + 128(b) + 512(h) ----------------
    zero_state(b0, h0);
    grid_sync();
    for (int t = 0; t < S_LEN; ++t) {
        unsigned long long acc[8] = {0ull,0ull,0ull,0ull,0ull,0ull,0ull,0ull};
        const float* hread = g_hbuf + (size_t)(t & 1) * BH;
        gemm_segment(x  + (size_t)t * BATCH * IN_DIM + (size_t)b0 * IN_DIM, IN_DIM, Wih0, IN_DIM / 32, h0,
                     acc, sAs[0], sAs[1], sWs[0], sWs[1]);
        gemm_segment(br + (size_t)t * BATCH * BR_DIM + (size_t)b0 * BR_DIM, BR_DIM, Wbh0, BR_DIM / 32, h0,
                     acc, sAs[0], sAs[1], sWs[0], sWs[1]);
        gemm_segment(hread + (size_t)b0 * HID, HID, Whh0, HID / 32, h0,
                     acc, sAs[0], sAs[1], sWs[0], sWs[1]);
        step_tail(acc, sWs[0], bias0, b0, h0,
                  g_hbuf + (size_t)((t + 1) & 1) * BH,
                  g_hs0 + (size_t)t * BH,
                  out + OFF_HN, out + OFF_CN, t == S_LEN - 1);
        grid_sync();
    }

    // ---------------- layer 1 (plain cell, zero init per reference): K = 512(hs0) + 512(h) ----------------
    zero_state(b0, h0);
    grid_sync();
    for (int t = 0; t < S_LEN; ++t) {
        unsigned long long acc[8] = {0ull,0ull,0ull,0ull,0ull,0ull,0ull,0ull};
        const float* hread = g_hbuf + (size_t)(t & 1) * BH;
        gemm_segment(g_hs0 + (size_t)t * BH + (size_t)b0 * HID, HID, Wih1, HID / 32, h0,
                     acc, sAs[0], sAs[1], sWs[0], sWs[1]);
        gemm_segment(hread + (size_t)b0 * HID, HID, Whh1, HID / 32, h0,
                     acc, sAs[0], sAs[1], sWs[0], sWs[1]);
        step_tail(acc, sWs[0], bias1, b0, h0,
                  g_hbuf + (size_t)((t + 1) & 1) * BH,
                  out + (size_t)t * BH,
                  out + OFF_HN + BH, out + OFF_CN + BH, t == S_LEN - 1);
        grid_sync();
    }
}

extern "C" void kernel_launch(void* const* d_in, const int* in_sizes, int n_in,
                              void* d_out, int out_size) {
    (void)in_sizes; (void)n_in; (void)out_size;
    const float* x     = (const float*)d_in[0];
    const float* br    = (const float*)d_in[1];
    const float* Wih0  = (const float*)d_in[2];
    const float* Wbh0  = (const float*)d_in[3];
    const float* Whh0  = (const float*)d_in[4];
    const float* bias0 = (const float*)d_in[5];
    const float* Wih1  = (const float*)d_in[6];
    const float* Whh1  = (const float*)d_in[7];
    const float* bias1 = (const float*)d_in[8];
    lstm_persistent<<<NBLK, NTHR>>>(x, br, Wih0, Wbh0, Whh0, bias0, Wih1, Whh1, bias1,
                                    (float*)d_out);
}